// round 11
// baseline (speedup 1.0000x reference)
#include <cuda_runtime.h>
#include <cuda_bf16.h>

// BlockMaskGenerator: B=8192 batches, NUM_BLOCKS=4 rectangles each, 64x64 grid.
// Output buffer is FLOAT32 (harness promotes the (bool,bool,int32,int32) tuple),
// flattened in reference order:
//   [0,       BS)  context_mask (= !target)       BS = B*4096
//   [BS,     2BS)  target_mask
//   [2BS,    3BS)  positions (stable argsort of ~target: True idx asc, then False idx asc)
//   [3BS, 3BS+B)   counts (popcount of target per batch)
// All values (0/1 masks, positions < 4096, counts <= 4096) are exact in f32.
//
// Store-bound: ~403 MB of output, ~0.4 MB of input.

#define Hd 64
#define Wd 64
#define Sd 4096
#define NB 4

__global__ __launch_bounds__(256) void bmg_kernel(
    const float* __restrict__ scales,
    const float* __restrict__ rtops,
    const float* __restrict__ rlefts,
    float* __restrict__ out, int B)
{
    const int b = blockIdx.x;
    const int t = threadIdx.x;

    __shared__ unsigned long long roww[64];
    __shared__ int pre[64];
    __shared__ int sTop[NB], sBh[NB], sLeft[NB], sBw[NB];
    __shared__ int warp0tot, sTotal;

    // ---- rectangle parameters (exact float32 semantics vs the jax reference) ----
    if (t < NB) {
        int idx = b * NB + t;
        // s = 0.15f + scales*0.05f  (separate rn mul + rn add; forbid FMA contraction)
        float s = __fadd_rn(0.15f, __fmul_rn(scales[idx], 0.05f));
        // area = trunc(s * 64 * 64)  (power-of-two scaling -> exact)
        int area = (int)(s * 4096.0f);
        // bh = clamp(trunc(sqrtf(area)), 1, 64) — double sqrt is immune to
        // fast-math sqrt.approx flipping truncation at perfect squares.
        int bh = (int)sqrt((double)area);
        bh = min(max(bh, 1), Hd);
        // bw = clamp(trunc(area / bh, IEEE f32 rn), 1, 64)
        int bw = (int)__fdiv_rn((float)area, (float)bh);
        bw = min(max(bw, 1), Wd);
        int maxT = max(Hd - bh + 1, 1);
        int maxL = max(Wd - bw + 1, 1);
        sTop[t]  = (int)__fmul_rn(rtops[idx],  (float)maxT);
        sLeft[t] = (int)__fmul_rn(rlefts[idx], (float)maxL);
        sBh[t] = bh;
        sBw[t] = bw;
    }
    __syncthreads();

    // ---- build 64-bit row words (bit c of roww[r] = target at (r,c)) ----
    unsigned long long w = 0ull;
    int cnt = 0;
    if (t < 64) {
        #pragma unroll
        for (int k = 0; k < NB; k++) {
            if (t >= sTop[k] && t < sTop[k] + sBh[k]) {
                int bw = sBw[k];
                unsigned long long m = (bw >= 64) ? ~0ull
                                                  : (((1ull << bw) - 1ull) << sLeft[k]);
                w |= m;
            }
        }
        roww[t] = w;
        cnt = __popcll(w);
    }

    // ---- exclusive prefix sum of per-row popcounts over 64 rows (2 warp scans) ----
    int inc = cnt;
    #pragma unroll
    for (int off = 1; off < 32; off <<= 1) {
        int v = __shfl_up_sync(0xffffffffu, inc, off);
        if ((t & 31) >= off) inc += v;
    }
    if (t == 31) warp0tot = inc;
    __syncthreads();
    if (t < 64) {
        int excl = inc - cnt + ((t >= 32) ? warp0tot : 0);
        pre[t] = excl;
        if (t == 63) sTotal = excl + cnt;
    }
    __syncthreads();

    const long long BS = (long long)B * Sd;
    const long long base = (long long)b * Sd;
    float* __restrict__ ctx = out + base;
    float* __restrict__ tgt = out + BS + base;
    float* __restrict__ pos = out + 2 * BS + base;

    const int r  = t >> 2;
    const int cb = (t & 3) * 16;
    const unsigned long long rw = roww[r];

    // ---- masks: each thread writes 16 positions as 4x float4 (coalesced 128b) ----
    {
        const int o = t * 16;
        #pragma unroll
        for (int j = 0; j < 16; j += 4) {
            float b0 = (float)((rw >> (cb + j))     & 1ull);
            float b1 = (float)((rw >> (cb + j + 1)) & 1ull);
            float b2 = (float)((rw >> (cb + j + 2)) & 1ull);
            float b3 = (float)((rw >> (cb + j + 3)) & 1ull);
            *reinterpret_cast<float4*>(tgt + o + j) =
                make_float4(b0, b1, b2, b3);
            *reinterpret_cast<float4*>(ctx + o + j) =
                make_float4(1.0f - b0, 1.0f - b1, 1.0f - b2, 1.0f - b3);
        }
    }

    // ---- positions: stable partition. True indices ascending occupy [0, total),
    //      False indices ascending occupy [total, 4096). Computed analytically. ----
    {
        unsigned long long beforeMask = (cb == 0) ? 0ull : (rw & ((1ull << cb) - 1ull));
        int tBefore = __popcll(beforeMask);
        int tOff = pre[r] + tBefore;                       // true-stream cursor
        int fOff = sTotal + (r * 64 + cb) - tOff;          // false-stream cursor
        float* tp = pos + tOff;
        float* fp = pos + fOff;
        #pragma unroll
        for (int c = 0; c < 16; c++) {
            int idx = r * 64 + cb + c;
            if ((rw >> (cb + c)) & 1ull) {
                *tp++ = (float)idx;
            } else {
                *fp++ = (float)idx;
            }
        }
    }

    if (t == 0) out[3 * BS + b] = (float)sTotal;
}

extern "C" void kernel_launch(void* const* d_in, const int* in_sizes, int n_in,
                              void* d_out, int out_size) {
    const float* scales = (const float*)d_in[0];
    const float* rtops  = (const float*)d_in[1];
    const float* rlefts = (const float*)d_in[2];
    int B = in_sizes[0] / NB;   // 32768 / 4 = 8192

    float* out = (float*)d_out;
    bmg_kernel<<<B, 256>>>(scales, rtops, rlefts, out, B);
}

// round 12
// speedup vs baseline: 2.8776x; 2.8776x over previous
#include <cuda_runtime.h>
#include <cuda_bf16.h>

// BlockMaskGenerator: B=8192 batches, NUM_BLOCKS=4 rectangles each, 64x64 grid.
// Output buffer is FLOAT32, flattened in reference order:
//   [0,       BS)  context_mask (= !target)       BS = B*4096
//   [BS,     2BS)  target_mask
//   [2BS,    3BS)  positions (stable argsort of ~target)
//   [3BS, 3BS+B)   counts
//
// R11: all global stores fully lane-coalesced (float4, consecutive lanes ->
// consecutive 16B); positions staged through SMEM; streaming stores (__stcs).

#define Hd 64
#define Wd 64
#define Sd 4096
#define NB 4

__global__ __launch_bounds__(256) void bmg_kernel(
    const float* __restrict__ scales,
    const float* __restrict__ rtops,
    const float* __restrict__ rlefts,
    float* __restrict__ out, int B)
{
    const int b = blockIdx.x;
    const int t = threadIdx.x;

    __shared__ unsigned long long roww[64];
    __shared__ int pre[64];
    __shared__ float posSh[Sd];          // 16 KB staging for positions
    __shared__ int sTop[NB], sBh[NB], sLeft[NB], sBw[NB];
    __shared__ int warp0tot, sTotal;

    // ---- rectangle parameters (exact float32 semantics vs the jax reference) ----
    if (t < NB) {
        int idx = b * NB + t;
        float s = __fadd_rn(0.15f, __fmul_rn(scales[idx], 0.05f));
        int area = (int)(s * 4096.0f);                 // power-of-two scale: exact
        int bh = (int)sqrt((double)area);              // immune to sqrt.approx
        bh = min(max(bh, 1), Hd);
        int bw = (int)__fdiv_rn((float)area, (float)bh);
        bw = min(max(bw, 1), Wd);
        int maxT = max(Hd - bh + 1, 1);
        int maxL = max(Wd - bw + 1, 1);
        sTop[t]  = (int)__fmul_rn(rtops[idx],  (float)maxT);
        sLeft[t] = (int)__fmul_rn(rlefts[idx], (float)maxL);
        sBh[t] = bh;
        sBw[t] = bw;
    }
    __syncthreads();

    // ---- build 64-bit row words (bit c of roww[r] = target at (r,c)) ----
    unsigned long long w = 0ull;
    int cnt = 0;
    if (t < 64) {
        #pragma unroll
        for (int k = 0; k < NB; k++) {
            if (t >= sTop[k] && t < sTop[k] + sBh[k]) {
                int bw = sBw[k];
                unsigned long long m = (bw >= 64) ? ~0ull
                                                  : (((1ull << bw) - 1ull) << sLeft[k]);
                w |= m;
            }
        }
        roww[t] = w;
        cnt = __popcll(w);
    }

    // ---- exclusive prefix sum of per-row popcounts (2 warp scans) ----
    int inc = cnt;
    #pragma unroll
    for (int off = 1; off < 32; off <<= 1) {
        int v = __shfl_up_sync(0xffffffffu, inc, off);
        if ((t & 31) >= off) inc += v;
    }
    if (t == 31) warp0tot = inc;
    __syncthreads();
    if (t < 64) {
        int excl = inc - cnt + ((t >= 32) ? warp0tot : 0);
        pre[t] = excl;
        if (t == 63) sTotal = excl + cnt;
    }
    __syncthreads();

    // ---- positions: stable partition scattered into SMEM (cheap), then
    //      flushed coalesced. True idx asc in [0,total), False idx asc after. ----
    {
        const int r  = t >> 2;
        const int cb = (t & 3) * 16;
        const unsigned long long rw = roww[r];
        unsigned long long beforeMask = (cb == 0) ? 0ull : (rw & ((1ull << cb) - 1ull));
        int tOff = pre[r] + __popcll(beforeMask);          // true-stream cursor
        int fOff = sTotal + (r * 64 + cb) - tOff;          // false-stream cursor
        #pragma unroll
        for (int c = 0; c < 16; c++) {
            int idx = r * 64 + cb + c;
            if ((rw >> (cb + c)) & 1ull) posSh[tOff++] = (float)idx;
            else                         posSh[fOff++] = (float)idx;
        }
    }
    __syncthreads();

    const long long BS = (long long)B * Sd;
    const long long base = (long long)b * Sd;
    float* __restrict__ ctx = out + base;
    float* __restrict__ tgt = out + BS + base;
    float* __restrict__ pos = out + 2 * BS + base;

    // ---- all global stores: lane-contiguous float4, streaming hint ----
    // element index e = p*1024 + t*4 : consecutive lanes -> consecutive 16B.
    #pragma unroll
    for (int p = 0; p < 4; p++) {
        const int e = p * 1024 + t * 4;
        // positions flush
        __stcs(reinterpret_cast<float4*>(pos + e),
               *reinterpret_cast<const float4*>(posSh + e));
        // masks: row = e>>6 (same for all 4 elems: e%64 <= 60), cols from bits
        const unsigned long long rw = roww[e >> 6];
        const int cb = e & 63;
        float b0 = (float)((rw >> (cb    )) & 1ull);
        float b1 = (float)((rw >> (cb + 1)) & 1ull);
        float b2 = (float)((rw >> (cb + 2)) & 1ull);
        float b3 = (float)((rw >> (cb + 3)) & 1ull);
        __stcs(reinterpret_cast<float4*>(tgt + e), make_float4(b0, b1, b2, b3));
        __stcs(reinterpret_cast<float4*>(ctx + e),
               make_float4(1.0f - b0, 1.0f - b1, 1.0f - b2, 1.0f - b3));
    }

    if (t == 0) __stcs(out + 3 * BS + b, (float)sTotal);
}

extern "C" void kernel_launch(void* const* d_in, const int* in_sizes, int n_in,
                              void* d_out, int out_size) {
    const float* scales = (const float*)d_in[0];
    const float* rtops  = (const float*)d_in[1];
    const float* rlefts = (const float*)d_in[2];
    int B = in_sizes[0] / NB;   // 32768 / 4 = 8192

    float* out = (float*)d_out;
    bmg_kernel<<<B, 256>>>(scales, rtops, rlefts, out, B);
}